// round 15
// baseline (speedup 1.0000x reference)
#include <cuda_runtime.h>
#include <cuda_bf16.h>
#include <cuda_fp16.h>
#include <math.h>

#define BB 4
#define T 1024
#define D 512
#define H 8
#define LL 2047
#define BT (BB*T)      // 4096
#define BL (BB*LL)     // 8188

__device__ __nv_bfloat16 g_yb[BT*D];           // LN output, bf16
__device__ __nv_bfloat16 g_wt[4*512*512];      // transposed bf16 weights: q,k,v,p
__device__ __half        g_wto[512*512];       // transposed fp16 Wo
__device__ __nv_bfloat16 g_posb[(size_t)BL*D]; // pos in bf16
__device__ float g_q[BT*D];    // q + bq (f32)
__device__ __half g_oh[BT*D];  // attention output, fp16
__device__ __nv_bfloat16 g_kb[BT*D];
__device__ __nv_bfloat16 g_pb[(size_t)BL*D];
__device__ __nv_bfloat16 g_vt[(size_t)BB*H*64*1024];  // [b*H+h][d][j]

// ---------------- helpers ----------------
__device__ __forceinline__ unsigned pack_bf16(float a, float b) {
    __nv_bfloat162 h = __floats2bfloat162_rn(a, b);
    return *(unsigned*)&h;
}
__device__ __forceinline__ unsigned sptr(const void* p) {
    return (unsigned)__cvta_generic_to_shared(p);
}
__device__ __forceinline__ void ldsm4(unsigned r[4], unsigned saddr) {
    asm volatile("ldmatrix.sync.aligned.m8n8.x4.shared.b16 {%0,%1,%2,%3}, [%4];"
        : "=r"(r[0]), "=r"(r[1]), "=r"(r[2]), "=r"(r[3]) : "r"(saddr));
}
__device__ __forceinline__ void mma_bf16(float d[4], const unsigned a[4], const unsigned b[2]) {
    asm volatile("mma.sync.aligned.m16n8k16.row.col.f32.bf16.bf16.f32 "
        "{%0,%1,%2,%3},{%4,%5,%6,%7},{%8,%9},{%0,%1,%2,%3};\n"
        : "+f"(d[0]), "+f"(d[1]), "+f"(d[2]), "+f"(d[3])
        : "r"(a[0]), "r"(a[1]), "r"(a[2]), "r"(a[3]), "r"(b[0]), "r"(b[1]));
}
__device__ __forceinline__ void mma_f16(float d[4], const unsigned a[4], const unsigned b[2]) {
    asm volatile("mma.sync.aligned.m16n8k16.row.col.f32.f16.f16.f32 "
        "{%0,%1,%2,%3},{%4,%5,%6,%7},{%8,%9},{%0,%1,%2,%3};\n"
        : "+f"(d[0]), "+f"(d[1]), "+f"(d[2]), "+f"(d[3])
        : "r"(a[0]), "r"(a[1]), "r"(a[2]), "r"(a[3]), "r"(b[0]), "r"(b[1]));
}
__device__ __forceinline__ void cpasync16(void* dst, const void* src, bool pred) {
    unsigned d = (unsigned)__cvta_generic_to_shared(dst);
    int sz = pred ? 16 : 0;
    asm volatile("cp.async.cg.shared.global [%0], [%1], 16, %2;\n"
                 :: "r"(d), "l"(src), "r"(sz));
}
__device__ __forceinline__ void gdc_wait() {
    asm volatile("griddepcontrol.wait;" ::: "memory");
}
__device__ __forceinline__ void gdc_launch() {
    asm volatile("griddepcontrol.launch_dependents;");
}

// ---------------- merged prep: weight transposes + pos->bf16 + LayerNorm ----------------
__global__ void prep_kernel(const float* __restrict__ x, const float* __restrict__ gamma,
                            const float* __restrict__ beta, const float* __restrict__ pos,
                            const float* __restrict__ Wq, const float* __restrict__ Wk,
                            const float* __restrict__ Wv, const float* __restrict__ Wp,
                            const float* __restrict__ Wo) {
    __shared__ float tile[32][33];
    __shared__ float ss[8], ssq[8], mb[2];
    int bid = blockIdx.x;
    int tid = threadIdx.x;
    if (bid < 1280) {
        int z = bid >> 8;
        int w = bid & 255;
        const float* W = (z == 0) ? Wq : (z == 1) ? Wk : (z == 2) ? Wv : (z == 3) ? Wp : Wo;
        int k0 = (w >> 4) * 32, n0 = (w & 15) * 32;
        #pragma unroll
        for (int p = 0; p < 4; p++) {
            int r = p * 8 + (tid >> 5), c = tid & 31;
            tile[r][c] = W[(size_t)(k0 + r) * 512 + n0 + c];
        }
        __syncthreads();
        #pragma unroll
        for (int p = 0; p < 4; p++) {
            int r = p * 8 + (tid >> 5), c = tid & 31;
            if (z < 4)
                g_wt[(size_t)z * 262144 + (size_t)(n0 + r) * 512 + k0 + c] =
                    __float2bfloat16_rn(tile[c][r]);
            else
                g_wto[(size_t)(n0 + r) * 512 + k0 + c] = __float2half_rn(tile[c][r]);
        }
    } else if (bid < 1280 + 4094) {
        size_t i = ((size_t)(bid - 1280) * 256 + tid) * 4;
        float4 v = *(const float4*)&pos[i];
        uint2 u;
        u.x = pack_bf16(v.x, v.y);
        u.y = pack_bf16(v.z, v.w);
        *(uint2*)&g_posb[i] = u;
    } else {
        int row = bid - 5374;
        const float* xr = x + (size_t)row * D;
        __nv_bfloat16* yr = g_yb + (size_t)row * D;
        float v0 = xr[tid], v1 = xr[tid + 256];
        float s = v0 + v1, sq = v0 * v0 + v1 * v1;
        #pragma unroll
        for (int o = 16; o > 0; o >>= 1) {
            s  += __shfl_xor_sync(0xFFFFFFFFu, s, o);
            sq += __shfl_xor_sync(0xFFFFFFFFu, sq, o);
        }
        if ((tid & 31) == 0) { ss[tid >> 5] = s; ssq[tid >> 5] = sq; }
        __syncthreads();
        if (tid == 0) {
            float S = 0.f, SQ = 0.f;
            #pragma unroll
            for (int i2 = 0; i2 < 8; i2++) { S += ss[i2]; SQ += ssq[i2]; }
            float mean = S * (1.0f / D);
            float var = SQ * (1.0f / D) - mean * mean;
            mb[0] = mean;
            mb[1] = rsqrtf(var + 1e-3f);
        }
        __syncthreads();
        float mean = mb[0], rstd = mb[1];
        yr[tid]       = __float2bfloat16_rn((v0 - mean) * rstd * gamma[tid]       + beta[tid]);
        yr[tid + 256] = __float2bfloat16_rn((v1 - mean) * rstd * gamma[tid + 256] + beta[tid + 256]);
    }
    gdc_launch();
}

// ---------------- unified bf16 projection: q/k/v/pos, 128x128x(K64) tiles, 3-stage ----------------
struct PSmem {
    unsigned As[3][128][36];
    unsigned Bs[3][128][36];
};

__device__ __forceinline__ void pall_load(PSmem* S, int buf,
                                          const __nv_bfloat16* A, const __nv_bfloat16* Bt,
                                          int i0, int j0, int kk, int M, int tid) {
    #pragma unroll
    for (int p = 0; p < 4; p++) {
        int idx = p * 256 + tid;
        int r = idx >> 3, c4 = (idx & 7) * 4;
        cpasync16(&S->As[buf][r][c4], &A[(size_t)(i0 + r) * 512 + kk + c4 * 2], (i0 + r) < M);
    }
    #pragma unroll
    for (int p = 0; p < 4; p++) {
        int idx = p * 256 + tid;
        int r = idx >> 3, c4 = (idx & 7) * 4;
        cpasync16(&S->Bs[buf][r][c4], &Bt[(size_t)(j0 + r) * 512 + kk + c4 * 2], true);
    }
    asm volatile("cp.async.commit_group;");
}

__global__ void __launch_bounds__(256, 2) projall_kernel(
        const float* __restrict__ bq, const float* __restrict__ bk,
        const float* __restrict__ bv) {
    extern __shared__ char raw[];
    PSmem* S = (PSmem*)raw;
    gdc_wait();
    int y = blockIdx.y;
    int zi, i0;
    if (y < 96) { zi = y >> 5; i0 = (y & 31) * 128; }
    else        { zi = 3;      i0 = (y - 96) * 128; }
    int M = (zi == 3) ? BL : BT;
    const __nv_bfloat16* A  = (zi == 3) ? g_posb : g_yb;
    const __nv_bfloat16* Bt = g_wt + (size_t)zi * 262144;
    const float* bias = (zi == 0) ? bq : (zi == 1) ? bk : (zi == 2) ? bv : nullptr;
    int j0 = blockIdx.x * 128;
    int tid = threadIdx.x;
    int warp = tid >> 5, lane = tid & 31;
    int wy = warp >> 2, wx = warp & 3;
    int g = lane >> 2, q = lane & 3;
    int rsel = lane & 15;
    int csel = (lane & 16) ? 4 : 0;
    int nsel = (lane & 7) + ((lane & 16) ? 8 : 0);
    int bcsel = (lane & 8) ? 4 : 0;
    float acc[4][4][4] = {};

    pall_load(S, 0, A, Bt, i0, j0, 0, M, tid);
    pall_load(S, 1, A, Bt, i0, j0, 64, M, tid);
    int buf = 0, ldb = 2;
    for (int s = 0; s < 8; s++) {
        if (s < 7) asm volatile("cp.async.wait_group 1;");
        else       asm volatile("cp.async.wait_group 0;");
        __syncthreads();
        if (s < 6) {
            pall_load(S, ldb, A, Bt, i0, j0, (s + 2) * 64, M, tid);
            ldb = (ldb == 2) ? 0 : ldb + 1;
        }
        unsigned abase[4], bbase[2];
        #pragma unroll
        for (int mt = 0; mt < 4; mt++)
            abase[mt] = sptr(&S->As[buf][wy * 64 + mt * 16 + rsel][csel]);
        #pragma unroll
        for (int ntp = 0; ntp < 2; ntp++)
            bbase[ntp] = sptr(&S->Bs[buf][wx * 32 + ntp * 16 + nsel][bcsel]);
        #pragma unroll
        for (int kb = 0; kb < 4; kb++) {
            unsigned afr[4][4], bfr[2][4];
            #pragma unroll
            for (int mt = 0; mt < 4; mt++) ldsm4(afr[mt], abase[mt] + kb * 32);
            #pragma unroll
            for (int ntp = 0; ntp < 2; ntp++) ldsm4(bfr[ntp], bbase[ntp] + kb * 32);
            #pragma unroll
            for (int mt = 0; mt < 4; mt++)
                #pragma unroll
                for (int nt = 0; nt < 4; nt++)
                    mma_bf16(acc[mt][nt], afr[mt], &bfr[nt >> 1][(nt & 1) * 2]);
        }
        buf = (buf == 2) ? 0 : buf + 1;
    }

    if (zi == 2) {
        __syncthreads();
        __nv_bfloat16* st = (__nv_bfloat16*)S->As;   // pitch 130 bf16
        #pragma unroll
        for (int mt = 0; mt < 4; mt++)
            #pragma unroll
            for (int nt = 0; nt < 4; nt++) {
                int cl = wx * 32 + nt * 8 + q * 2;
                float b0 = bias[j0 + cl], b1 = bias[j0 + cl + 1];
                #pragma unroll
                for (int half = 0; half < 2; half++) {
                    int rl = wy * 64 + mt * 16 + g + half * 8;
                    *(unsigned*)&st[rl * 130 + cl] =
                        pack_bf16(acc[mt][nt][half * 2 + 0] + b0,
                                  acc[mt][nt][half * 2 + 1] + b1);
                }
            }
        __syncthreads();
        int b_ = i0 >> 10;
        int irow = i0 & 1023;
        #pragma unroll
        for (int rep = 0; rep < 32; rep++) {
            int dp = rep * 4 + (tid >> 6);
            int m2 = (tid & 63) * 2;
            int gc = j0 + dp;
            int h_ = gc >> 6, d_ = gc & 63;
            __nv_bfloat162 hh;
            hh.x = st[m2 * 130 + dp];
            hh.y = st[(m2 + 1) * 130 + dp];
            *(unsigned*)&g_vt[(((size_t)(b_ * 8 + h_)) * 64 + d_) * 1024 + irow + m2] =
                *(unsigned*)&hh;
        }
        gdc_launch();
        return;
    }

    #pragma unroll
    for (int mt = 0; mt < 4; mt++)
        #pragma unroll
        for (int nt = 0; nt < 4; nt++) {
            int c = j0 + wx * 32 + nt * 8 + q * 2;
            float b0 = bias ? bias[c] : 0.f;
            float b1 = bias ? bias[c + 1] : 0.f;
            #pragma unroll
            for (int half = 0; half < 2; half++) {
                int rr = i0 + wy * 64 + mt * 16 + g + half * 8;
                if (rr >= M) continue;
                float e0 = acc[mt][nt][half * 2 + 0] + b0;
                float e1 = acc[mt][nt][half * 2 + 1] + b1;
                if (zi == 0)
                    *(float2*)&g_q[(size_t)rr * 512 + c] = make_float2(e0, e1);
                else if (zi == 1)
                    ((unsigned*)g_kb)[((size_t)rr * 512 + c) >> 1] = pack_bf16(e0, e1);
                else
                    ((unsigned*)g_pb)[((size_t)rr * 512 + c) >> 1] = pack_bf16(e0, e1);
            }
        }
    gdc_launch();
}

// ---------------- fp16 output projection: out = o @ Wo^T + bo + x; x prefetched ----------------
struct POSmem {
    unsigned As[2][64][36];
    unsigned Bs[2][128][36];
    float Xs[64][132];    // pitch 132 floats = 528 B (16B multiple for cp.async)
};

__device__ __forceinline__ void pout_load(POSmem* S, int buf, int i0, int j0, int kk, int tid) {
    #pragma unroll
    for (int p = 0; p < 2; p++) {
        int idx = p * 256 + tid;
        int r = idx >> 3, c4 = (idx & 7) * 4;
        cpasync16(&S->As[buf][r][c4], &g_oh[(size_t)(i0 + r) * 512 + kk + c4 * 2], true);
    }
    #pragma unroll
    for (int p = 0; p < 4; p++) {
        int idx = p * 256 + tid;
        int r = idx >> 3, c4 = (idx & 7) * 4;
        cpasync16(&S->Bs[buf][r][c4], &g_wto[(size_t)(j0 + r) * 512 + kk + c4 * 2], true);
    }
    asm volatile("cp.async.commit_group;");
}

__global__ void __launch_bounds__(256, 2) projout_kernel(
        const float* __restrict__ bo, const float* __restrict__ x,
        float* __restrict__ out) {
    extern __shared__ char raw[];
    POSmem* S = (POSmem*)raw;
    gdc_wait();
    int i0 = blockIdx.y * 64, j0 = blockIdx.x * 128;
    int tid = threadIdx.x;
    int warp = tid >> 5, lane = tid & 31;
    int wy = warp >> 2, wx = warp & 3;
    int g = lane >> 2, q = lane & 3;
    int rsel = lane & 15;
    int csel = (lane & 16) ? 4 : 0;
    int nsel = (lane & 7) + ((lane & 16) ? 8 : 0);
    int bcsel = (lane & 8) ? 4 : 0;
    float acc[2][4][4] = {};

    // prefetch residual x tile
    #pragma unroll
    for (int p = 0; p < 8; p++) {
        int idx = p * 256 + tid;
        int r = idx >> 5, c4 = (idx & 31) * 4;
        cpasync16(&S->Xs[r][c4], &x[(size_t)(i0 + r) * 512 + j0 + c4], true);
    }
    asm volatile("cp.async.commit_group;");

    pout_load(S, 0, i0, j0, 0, tid);
    for (int s = 0; s < 8; s++) {
        asm volatile("cp.async.wait_group 0;");
        __syncthreads();
        if (s < 7)
            pout_load(S, (s + 1) & 1, i0, j0, (s + 1) * 64, tid);  // distinct from live buf
        int buf = s & 1;
        unsigned abase[2], bbase[2];
        #pragma unroll
        for (int mt = 0; mt < 2; mt++)
            abase[mt] = sptr(&S->As[buf][wy * 32 + mt * 16 + rsel][csel]);
        #pragma unroll
        for (int ntp = 0; ntp < 2; ntp++)
            bbase[ntp] = sptr(&S->Bs[buf][wx * 32 + ntp * 16 + nsel][bcsel]);
        #pragma unroll
        for (int kb = 0; kb < 4; kb++) {
            unsigned afr[2][4], bfr[2][4];
            #pragma unroll
            for (int mt = 0; mt < 2; mt++) ldsm4(afr[mt], abase[mt] + kb * 32);
            #pragma unroll
            for (int ntp = 0; ntp < 2; ntp++) ldsm4(bfr[ntp], bbase[ntp] + kb * 32);
            #pragma unroll
            for (int mt = 0; mt < 2; mt++)
                #pragma unroll
                for (int nt = 0; nt < 4; nt++)
                    mma_f16(acc[mt][nt], afr[mt], &bfr[nt >> 1][(nt & 1) * 2]);
        }
    }
    #pragma unroll
    for (int mt = 0; mt < 2; mt++)
        #pragma unroll
        for (int nt = 0; nt < 4; nt++) {
            int cl = wx * 32 + nt * 8 + q * 2;
            int c = j0 + cl;
            float b0 = bo[c], b1 = bo[c + 1];
            #pragma unroll
            for (int half = 0; half < 2; half++) {
                int rl = wy * 32 + mt * 16 + g + half * 8;
                int rr = i0 + rl;
                float e0 = acc[mt][nt][half * 2 + 0] + b0 + S->Xs[rl][cl];
                float e1 = acc[mt][nt][half * 2 + 1] + b1 + S->Xs[rl][cl + 1];
                *(float2*)&out[(size_t)rr * 512 + c] = make_float2(e0, e1);
            }
        }
}

// ---------------- flash attention: 128-row i-tiles, 8 warps, 1 CTA/SM ----------------
struct FlashSmem {
    unsigned Ks[2][64][36];
    unsigned Ps[2][64][36];
    unsigned Vt[2][64][36];
    __nv_bfloat16 R[128][264];
    float Qs[128][68];
    float cbS[64], pbS[64];
};

__device__ __forceinline__ void pos_chunk(FlashSmem* S, int stage, int cbase,
                                          const unsigned apf[4][4], int row0,
                                          int nsel, int bcsel, int q) {
    float accP[8][4] = {};
    #pragma unroll
    for (int ntp = 0; ntp < 4; ntp++) {
        unsigned base = sptr(&S->Ps[stage][ntp * 16 + nsel][bcsel]);
        #pragma unroll
        for (int kb = 0; kb < 4; kb++) {
            unsigned bfr[4];
            ldsm4(bfr, base + kb * 32);
            mma_bf16(accP[ntp * 2],     apf[kb], bfr);
            mma_bf16(accP[ntp * 2 + 1], apf[kb], bfr + 2);
        }
    }
    #pragma unroll
    for (int nt = 0; nt < 8; nt++) {
        int s0 = (cbase + nt * 8 + 2 * q) & 255;
        *(__nv_bfloat162*)&S->R[row0][s0]     = __floats2bfloat162_rn(accP[nt][0], accP[nt][1]);
        *(__nv_bfloat162*)&S->R[row0 + 8][s0] = __floats2bfloat162_rn(accP[nt][2], accP[nt][3]);
    }
}

__global__ void __launch_bounds__(256, 1) flash_kernel(const float* __restrict__ cb,
                                                       const float* __restrict__ pb) {
    extern __shared__ char raw[];
    FlashSmem* S = (FlashSmem*)raw;
    gdc_wait();
    int z = blockIdx.y; int b = z >> 3, h = z & 7;
    int i0 = blockIdx.x * 128;
    int tid = threadIdx.x;
    int warp = tid >> 5, lane = tid & 31;
    int g = lane >> 2, q = lane & 3;
    int row0 = warp * 16 + g;               // 0..127
    int nsel = (lane & 7) + ((lane & 16) ? 8 : 0);
    int bcsel = (lane & 8) ? 4 : 0;
    const int base0 = 1024 - i0 - 128;      // >= 0 (i0 <= 896), multiple of 64

    // prologue: Qs (128 rows f32) + P chunks 0,1
    const float* qsrc = g_q + ((size_t)(b * T + i0)) * D + h * 64;
    #pragma unroll
    for (int p = 0; p < 8; p++) {
        int idx = p * 256 + tid;
        int r = idx >> 4, c4 = (idx & 15) * 4;
        cpasync16(&S->Qs[r][c4], &qsrc[(size_t)r * D + c4], true);
    }
    #pragma unroll
    for (int p = 0; p < 2; p++) {
        int idx = p * 256 + tid;
        int r = idx >> 3, c8 = (idx & 7) * 8;
        int l0 = base0 + r;      l0 = min(max(l0, 0), LL - 1);
        int l1 = base0 + 64 + r; l1 = min(max(l1, 0), LL - 1);
        cpasync16(&S->Ps[0][r][c8 >> 1], &g_pb[((size_t)(b * LL + l0)) * D + h * 64 + c8], true);
        cpasync16(&S->Ps[1][r][c8 >> 1], &g_pb[((size_t)(b * LL + l1)) * D + h * 64 + c8], true);
    }
    asm volatile("cp.async.commit_group;");
    if (tid < 16) {
        *(float4*)&S->cbS[tid * 4] = *(const float4*)&cb[h * 64 + tid * 4];
        *(float4*)&S->pbS[tid * 4] = *(const float4*)&pb[h * 64 + tid * 4];
    }

    float gfixv = 0.f;
    if (i0 == 0 && warp == 0) {
        float a0 = __bfloat162float(__float2bfloat16_rn(
            g_q[((size_t)(b * T + 1)) * D + h * 64 + lane] + pb[h * 64 + lane]));
        float a1 = __bfloat162float(__float2bfloat16_rn(
            g_q[((size_t)(b * T + 1)) * D + h * 64 + lane + 32] + pb[h * 64 + lane + 32]));
        float p0 = __bfloat162float(g_pb[((size_t)(b * LL)) * D + h * 64 + lane]);
        float p1 = __bfloat162float(g_pb[((size_t)(b * LL)) * D + h * 64 + lane + 32]);
        float sd = a0 * p0 + a1 * p1;
        #pragma unroll
        for (int o = 16; o > 0; o >>= 1) sd += __shfl_xor_sync(0xFFFFFFFFu, sd, o);
        gfixv = sd;
    }

    asm volatile("cp.async.wait_group 0;");
    __syncthreads();

    unsigned acf[4][4], apf[4][4];
    #pragma unroll
    for (int kb = 0; kb < 4; kb++) {
        int k0 = kb * 16 + 2 * q;
        float q00 = S->Qs[row0][k0],       q01 = S->Qs[row0][k0 + 1];
        float q10 = S->Qs[row0 + 8][k0],   q11 = S->Qs[row0 + 8][k0 + 1];
        float q02 = S->Qs[row0][k0 + 8],   q03 = S->Qs[row0][k0 + 9];
        float q12 = S->Qs[row0 + 8][k0 + 8], q13 = S->Qs[row0 + 8][k0 + 9];
        float c0 = S->cbS[k0], c1 = S->cbS[k0 + 1], c8v = S->cbS[k0 + 8], c9 = S->cbS[k0 + 9];
        float p0 = S->pbS[k0], p1 = S->pbS[k0 + 1], p8 = S->pbS[k0 + 8], p9 = S->pbS[k0 + 9];
        acf[kb][0] = pack_bf16(q00 + c0, q01 + c1);
        acf[kb][1] = pack_bf16(q10 + c0, q11 + c1);
        acf[kb][2] = pack_bf16(q02 + c8v, q03 + c9);
        acf[kb][3] = pack_bf16(q12 + c8v, q13 + c9);
        apf[kb][0] = pack_bf16(q00 + p0, q01 + p1);
        apf[kb][1] = pack_bf16(q10 + p0, q11 + p1);
        apf[kb][2] = pack_bf16(q02 + p8, q03 + p9);
        apf[kb][3] = pack_bf16(q12 + p8, q13 + p9);
    }

    pos_chunk(S, 0, base0, apf, row0, nsel, bcsel, q);
    pos_chunk(S, 1, base0 + 64, apf, row0, nsel, bcsel, q);
    __syncthreads();
    #pragma unroll
    for (int p = 0; p < 2; p++) {
        int idx = p * 256 + tid;
        int r = idx >> 3, c8 = (idx & 7) * 8;
        int l = base0 + 128 + r; l = min(max(l, 0), LL - 1);
        cpasync16(&S->Ps[0][r][c8 >> 1], &g_pb[((size_t)(b * LL + l)) * D + h * 64 + c8], true);
    }
    asm volatile("cp.async.commit_group;");
    asm volatile("cp.async.wait_group 0;");
    __syncthreads();
    pos_chunk(S, 0, base0 + 128, apf, row0, nsel, bcsel, q);
    __syncthreads();

    {
        const __nv_bfloat16* kb_ = g_kb + ((size_t)(b * T)) * D + h * 64;
        const __nv_bfloat16* vt_ = g_vt + ((size_t)z) * 64 * 1024;
        #pragma unroll
        for (int p = 0; p < 2; p++) {
            int idx = p * 256 + tid;
            int r = idx >> 3, c8 = (idx & 7) * 8;
            cpasync16(&S->Ks[0][r][c8 >> 1], &kb_[(size_t)r * D + c8], true);
            cpasync16(&S->Vt[0][r][c8 >> 1], &vt_[(size_t)r * 1024 + c8], true);
            int l = base0 + 192 + r; l = min(max(l, 0), LL - 1);
            cpasync16(&S->Ps[0][r][c8 >> 1], &g_pb[((size_t)(b * LL + l)) * D + h * 64 + c8], true);
        }
        asm volatile("cp.async.commit_group;");
    }

    float accO[8][4] = {};
    float sumA = 0.f, sumB = 0.f;

    for (int jt = 0; jt < 16; jt++) {
        asm volatile("cp.async.wait_group 0;");
        __syncthreads();
        int st = jt & 1;
        if (jt < 15) {
            int st2 = st ^ 1;
            const __nv_bfloat16* kb_ = g_kb + ((size_t)(b * T + (jt + 1) * 64)) * D + h * 64;
            const __nv_bfloat16* vt_ = g_vt + ((size_t)z) * 64 * 1024 + (jt + 1) * 64;
            #pragma unroll
            for (int p = 0; p < 2; p++) {
                int idx = p * 256 + tid;
                int r = idx >> 3, c8 = (idx & 7) * 8;
                cpasync16(&S->Ks[st2][r][c8 >> 1], &kb_[(size_t)r * D + c8], true);
                cpasync16(&S->Vt[st2][r][c8 >> 1], &vt_[(size_t)r * 1024 + c8], true);
                int l = base0 + 192 + 64 * (jt + 1) + r; l = min(max(l, 0), LL - 1);
                cpasync16(&S->Ps[st2][r][c8 >> 1], &g_pb[((size_t)(b * LL + l)) * D + h * 64 + c8], true);
            }
            asm volatile("cp.async.commit_group;");
        }

        float accC[8][4] = {};
        #pragma unroll
        for (int ntp = 0; ntp < 4; ntp++) {
            unsigned base = sptr(&S->Ks[st][ntp * 16 + nsel][bcsel]);
            #pragma unroll
            for (int kb2 = 0; kb2 < 4; kb2++) {
                unsigned bfr[4];
                ldsm4(bfr, base + kb2 * 32);
                mma_bf16(accC[ntp * 2],     acf[kb2], bfr);
                mma_bf16(accC[ntp * 2 + 1], acf[kb2], bfr + 2);
            }
        }
        if (jt < 15) pos_chunk(S, st, base0 + 192 + 64 * jt, apf, row0, nsel, bcsel, q);

        unsigned vbase[4];
        #pragma unroll
        for (int n2p = 0; n2p < 4; n2p++)
            vbase[n2p] = sptr(&S->Vt[st][n2p * 16 + nsel][bcsel]);

        int basew = 1024 + 64 * jt - i0;
        bool fixc = (i0 == 0) && (jt == 15) && (warp == 0) && (g == 0) && (q == 3);
        #pragma unroll
        for (int kb2 = 0; kb2 < 4; kb2++) {
            unsigned a[4];
            #pragma unroll
            for (int half = 0; half < 2; half++) {
                int nt = kb2 * 2 + half;
                int jl = nt * 8 + 2 * q;
                int il0 = row0, il1 = row0 + 8;
                float r00 = __bfloat162float(S->R[il0][(basew + jl - il0) & 255]);
                float r01 = __bfloat162float(S->R[il0][(basew + jl + 1 - il0) & 255]);
                float r10 = __bfloat162float(S->R[il1][(basew + jl - il1) & 255]);
                float r11 = __bfloat162float(S->R[il1][(basew + jl + 1 - il1) & 255]);
                if (fixc && nt == 7) r01 = gfixv;
                float e0 = __expf((accC[nt][0] + r00) * 0.125f);
                float e1 = __expf((accC[nt][1] + r01) * 0.125f);
                float e2 = __expf((accC[nt][2] + r10) * 0.125f);
                float e3 = __expf((accC[nt][3] + r11) * 0.125f);
                sumA += e0 + e1; sumB += e2 + e3;
                a[half * 2]     = pack_bf16(e0, e1);
                a[half * 2 + 1] = pack_bf16(e2, e3);
            }
            #pragma unroll
            for (int n2p = 0; n2p < 4; n2p++) {
                unsigned vfr[4];
                ldsm4(vfr, vbase[n2p] + kb2 * 32);
                mma_bf16(accO[n2p * 2],     a, vfr);
                mma_bf16(accO[n2p * 2 + 1], a, vfr + 2);
            }
        }
    }

    sumA += __shfl_xor_sync(0xFFFFFFFFu, sumA, 1);
    sumA += __shfl_xor_sync(0xFFFFFFFFu, sumA, 2);
    sumB += __shfl_xor_sync(0xFFFFFFFFu, sumB, 1);
    sumB += __shfl_xor_sync(0xFFFFFFFFu, sumB, 2);
    float invA = 1.f / sumA, invB = 1.f / sumB;
    #pragma unroll
    for (int n2 = 0; n2 < 8; n2++) {
        int col = h * 64 + n2 * 8 + 2 * q;
        size_t r = (size_t)(b * T + i0 + row0);
        __half2 h0 = __floats2half2_rn(accO[n2][0] * invA, accO[n2][1] * invA);
        __half2 h1 = __floats2half2_rn(accO[n2][2] * invB, accO[n2][3] * invB);
        *(unsigned*)&g_oh[r * D + col] = *(unsigned*)&h0;
        *(unsigned*)&g_oh[(r + 8) * D + col] = *(unsigned*)&h1;
    }
    gdc_launch();
}

extern "C" void kernel_launch(void* const* d_in, const int* in_sizes, int n_in,
                              void* d_out, int out_size) {
    const float* x     = (const float*)d_in[0];
    const float* pos   = (const float*)d_in[1];
    const float* cb    = (const float*)d_in[2];
    const float* pb    = (const float*)d_in[3];
    const float* gamma = (const float*)d_in[4];
    const float* beta  = (const float*)d_in[5];
    const float* Wq    = (const float*)d_in[6];
    const float* bq    = (const float*)d_in[7];
    const float* Wk    = (const float*)d_in[8];
    const float* bk    = (const float*)d_in[9];
    const float* Wv    = (const float*)d_in[10];
    const float* bv    = (const float*)d_in[11];
    const float* Wp    = (const float*)d_in[12];
    const float* Wo    = (const float*)d_in[13];
    const float* bo    = (const float*)d_in[14];
    float* out = (float*)d_out;

    cudaFuncSetAttribute(projall_kernel, cudaFuncAttributeMaxDynamicSharedMemorySize,
                         (int)sizeof(PSmem));
    cudaFuncSetAttribute(projout_kernel, cudaFuncAttributeMaxDynamicSharedMemorySize,
                         (int)sizeof(POSmem));
    cudaFuncSetAttribute(flash_kernel, cudaFuncAttributeMaxDynamicSharedMemorySize,
                         (int)sizeof(FlashSmem));

    // PDL launch attribute
    cudaLaunchAttribute pdl[1];
    pdl[0].id = cudaLaunchAttributeProgrammaticStreamSerialization;
    pdl[0].val.programmaticStreamSerializationAllowed = 1;

    // 1. merged prep: 5 weight transposes + pos convert (float4) + LayerNorm
    prep_kernel<<<9470, 256>>>(x, gamma, beta, pos, Wq, Wk, Wv, Wp, Wo);

    // 2. unified projections (q/k/v/pos, bf16, ldmatrix, 3-stage pipeline)
    {
        cudaLaunchConfig_t cfg = {};
        cfg.gridDim = dim3(4, 160);
        cfg.blockDim = dim3(256);
        cfg.dynamicSmemBytes = sizeof(PSmem);
        cfg.attrs = pdl; cfg.numAttrs = 1;
        cudaLaunchKernelEx(&cfg, projall_kernel, bq, bk, bv);
    }

    // 3. fused flash attention (128-row tiles, 8 warps)
    {
        cudaLaunchConfig_t cfg = {};
        cfg.gridDim = dim3(8, 32);
        cfg.blockDim = dim3(256);
        cfg.dynamicSmemBytes = sizeof(FlashSmem);
        cfg.attrs = pdl; cfg.numAttrs = 1;
        cudaLaunchKernelEx(&cfg, flash_kernel, cb, pb);
    }

    // 4. output projection (fp16 mma) + bias + residual (x prefetched)
    {
        cudaLaunchConfig_t cfg = {};
        cfg.gridDim = dim3(4, 64);
        cfg.blockDim = dim3(256);
        cfg.dynamicSmemBytes = sizeof(POSmem);
        cfg.attrs = pdl; cfg.numAttrs = 1;
        cudaLaunchKernelEx(&cfg, projout_kernel, bo, x, out);
    }
}

// round 16
// speedup vs baseline: 1.0341x; 1.0341x over previous
#include <cuda_runtime.h>
#include <cuda_bf16.h>
#include <cuda_fp16.h>
#include <math.h>

#define BB 4
#define T 1024
#define D 512
#define H 8
#define LL 2047
#define BT (BB*T)      // 4096
#define BL (BB*LL)     // 8188

__device__ __nv_bfloat16 g_yb[BT*D];           // LN output, bf16
__device__ __nv_bfloat16 g_wt[4*512*512];      // transposed bf16 weights: q,k,v,p
__device__ __half        g_wto[512*512];       // transposed fp16 Wo
__device__ __nv_bfloat16 g_posb[(size_t)BL*D]; // pos in bf16
__device__ float g_q[BT*D];    // q + bq (f32)
__device__ __half g_oh[BT*D];  // attention output, fp16
__device__ __nv_bfloat16 g_kb[BT*D];
__device__ __nv_bfloat16 g_pb[(size_t)BL*D];
__device__ __nv_bfloat16 g_vt[(size_t)BB*H*64*1024];  // [b*H+h][d][j]

// ---------------- helpers ----------------
__device__ __forceinline__ unsigned pack_bf16(float a, float b) {
    __nv_bfloat162 h = __floats2bfloat162_rn(a, b);
    return *(unsigned*)&h;
}
__device__ __forceinline__ unsigned sptr(const void* p) {
    return (unsigned)__cvta_generic_to_shared(p);
}
__device__ __forceinline__ void ldsm4(unsigned r[4], unsigned saddr) {
    asm volatile("ldmatrix.sync.aligned.m8n8.x4.shared.b16 {%0,%1,%2,%3}, [%4];"
        : "=r"(r[0]), "=r"(r[1]), "=r"(r[2]), "=r"(r[3]) : "r"(saddr));
}
__device__ __forceinline__ void mma_bf16(float d[4], const unsigned a[4], const unsigned b[2]) {
    asm volatile("mma.sync.aligned.m16n8k16.row.col.f32.bf16.bf16.f32 "
        "{%0,%1,%2,%3},{%4,%5,%6,%7},{%8,%9},{%0,%1,%2,%3};\n"
        : "+f"(d[0]), "+f"(d[1]), "+f"(d[2]), "+f"(d[3])
        : "r"(a[0]), "r"(a[1]), "r"(a[2]), "r"(a[3]), "r"(b[0]), "r"(b[1]));
}
__device__ __forceinline__ void mma_f16(float d[4], const unsigned a[4], const unsigned b[2]) {
    asm volatile("mma.sync.aligned.m16n8k16.row.col.f32.f16.f16.f32 "
        "{%0,%1,%2,%3},{%4,%5,%6,%7},{%8,%9},{%0,%1,%2,%3};\n"
        : "+f"(d[0]), "+f"(d[1]), "+f"(d[2]), "+f"(d[3])
        : "r"(a[0]), "r"(a[1]), "r"(a[2]), "r"(a[3]), "r"(b[0]), "r"(b[1]));
}
__device__ __forceinline__ void cpasync16(void* dst, const void* src, bool pred) {
    unsigned d = (unsigned)__cvta_generic_to_shared(dst);
    int sz = pred ? 16 : 0;
    asm volatile("cp.async.cg.shared.global [%0], [%1], 16, %2;\n"
                 :: "r"(d), "l"(src), "r"(sz));
}
__device__ __forceinline__ void gdc_wait() {
    asm volatile("griddepcontrol.wait;" ::: "memory");
}
__device__ __forceinline__ void gdc_launch() {
    asm volatile("griddepcontrol.launch_dependents;");
}

// ---------------- merged prep: weight transposes + pos->bf16 + LayerNorm ----------------
__global__ void prep_kernel(const float* __restrict__ x, const float* __restrict__ gamma,
                            const float* __restrict__ beta, const float* __restrict__ pos,
                            const float* __restrict__ Wq, const float* __restrict__ Wk,
                            const float* __restrict__ Wv, const float* __restrict__ Wp,
                            const float* __restrict__ Wo) {
    __shared__ float tile[32][33];
    __shared__ float ss[8], ssq[8], mb[2];
    int bid = blockIdx.x;
    int tid = threadIdx.x;
    if (bid < 1280) {
        int z = bid >> 8;
        int w = bid & 255;
        const float* W = (z == 0) ? Wq : (z == 1) ? Wk : (z == 2) ? Wv : (z == 3) ? Wp : Wo;
        int k0 = (w >> 4) * 32, n0 = (w & 15) * 32;
        #pragma unroll
        for (int p = 0; p < 4; p++) {
            int r = p * 8 + (tid >> 5), c = tid & 31;
            tile[r][c] = W[(size_t)(k0 + r) * 512 + n0 + c];
        }
        __syncthreads();
        #pragma unroll
        for (int p = 0; p < 4; p++) {
            int r = p * 8 + (tid >> 5), c = tid & 31;
            if (z < 4)
                g_wt[(size_t)z * 262144 + (size_t)(n0 + r) * 512 + k0 + c] =
                    __float2bfloat16_rn(tile[c][r]);
            else
                g_wto[(size_t)(n0 + r) * 512 + k0 + c] = __float2half_rn(tile[c][r]);
        }
    } else if (bid < 1280 + 4094) {
        size_t i = ((size_t)(bid - 1280) * 256 + tid) * 4;
        float4 v = *(const float4*)&pos[i];
        uint2 u;
        u.x = pack_bf16(v.x, v.y);
        u.y = pack_bf16(v.z, v.w);
        *(uint2*)&g_posb[i] = u;
    } else {
        int row = bid - 5374;
        const float* xr = x + (size_t)row * D;
        __nv_bfloat16* yr = g_yb + (size_t)row * D;
        float v0 = xr[tid], v1 = xr[tid + 256];
        float s = v0 + v1, sq = v0 * v0 + v1 * v1;
        #pragma unroll
        for (int o = 16; o > 0; o >>= 1) {
            s  += __shfl_xor_sync(0xFFFFFFFFu, s, o);
            sq += __shfl_xor_sync(0xFFFFFFFFu, sq, o);
        }
        if ((tid & 31) == 0) { ss[tid >> 5] = s; ssq[tid >> 5] = sq; }
        __syncthreads();
        if (tid == 0) {
            float S = 0.f, SQ = 0.f;
            #pragma unroll
            for (int i2 = 0; i2 < 8; i2++) { S += ss[i2]; SQ += ssq[i2]; }
            float mean = S * (1.0f / D);
            float var = SQ * (1.0f / D) - mean * mean;
            mb[0] = mean;
            mb[1] = rsqrtf(var + 1e-3f);
        }
        __syncthreads();
        float mean = mb[0], rstd = mb[1];
        yr[tid]       = __float2bfloat16_rn((v0 - mean) * rstd * gamma[tid]       + beta[tid]);
        yr[tid + 256] = __float2bfloat16_rn((v1 - mean) * rstd * gamma[tid + 256] + beta[tid + 256]);
    }
    gdc_launch();
}

// ---------------- unified bf16 projection: q/k/v/pos, 128x128x(K64) tiles, 3-stage ----------------
struct PSmem {
    unsigned As[3][128][36];
    unsigned Bs[3][128][36];
};

__device__ __forceinline__ void pall_load(PSmem* S, int buf,
                                          const __nv_bfloat16* A, const __nv_bfloat16* Bt,
                                          int i0, int j0, int kk, int M, int tid) {
    #pragma unroll
    for (int p = 0; p < 4; p++) {
        int idx = p * 256 + tid;
        int r = idx >> 3, c4 = (idx & 7) * 4;
        cpasync16(&S->As[buf][r][c4], &A[(size_t)(i0 + r) * 512 + kk + c4 * 2], (i0 + r) < M);
    }
    #pragma unroll
    for (int p = 0; p < 4; p++) {
        int idx = p * 256 + tid;
        int r = idx >> 3, c4 = (idx & 7) * 4;
        cpasync16(&S->Bs[buf][r][c4], &Bt[(size_t)(j0 + r) * 512 + kk + c4 * 2], true);
    }
    asm volatile("cp.async.commit_group;");
}

__global__ void __launch_bounds__(256, 2) projall_kernel(
        const float* __restrict__ bq, const float* __restrict__ bk,
        const float* __restrict__ bv) {
    extern __shared__ char raw[];
    PSmem* S = (PSmem*)raw;
    gdc_wait();
    int y = blockIdx.y;
    int zi, i0;
    if (y < 96) { zi = y >> 5; i0 = (y & 31) * 128; }
    else        { zi = 3;      i0 = (y - 96) * 128; }
    int M = (zi == 3) ? BL : BT;
    const __nv_bfloat16* A  = (zi == 3) ? g_posb : g_yb;
    const __nv_bfloat16* Bt = g_wt + (size_t)zi * 262144;
    const float* bias = (zi == 0) ? bq : (zi == 1) ? bk : (zi == 2) ? bv : nullptr;
    int j0 = blockIdx.x * 128;
    int tid = threadIdx.x;
    int warp = tid >> 5, lane = tid & 31;
    int wy = warp >> 2, wx = warp & 3;
    int g = lane >> 2, q = lane & 3;
    int rsel = lane & 15;
    int csel = (lane & 16) ? 4 : 0;
    int nsel = (lane & 7) + ((lane & 16) ? 8 : 0);
    int bcsel = (lane & 8) ? 4 : 0;
    float acc[4][4][4] = {};

    pall_load(S, 0, A, Bt, i0, j0, 0, M, tid);
    pall_load(S, 1, A, Bt, i0, j0, 64, M, tid);
    int buf = 0, ldb = 2;
    for (int s = 0; s < 8; s++) {
        if (s < 7) asm volatile("cp.async.wait_group 1;");
        else       asm volatile("cp.async.wait_group 0;");
        __syncthreads();
        if (s < 6) {
            pall_load(S, ldb, A, Bt, i0, j0, (s + 2) * 64, M, tid);
            ldb = (ldb == 2) ? 0 : ldb + 1;
        }
        unsigned abase[4], bbase[2];
        #pragma unroll
        for (int mt = 0; mt < 4; mt++)
            abase[mt] = sptr(&S->As[buf][wy * 64 + mt * 16 + rsel][csel]);
        #pragma unroll
        for (int ntp = 0; ntp < 2; ntp++)
            bbase[ntp] = sptr(&S->Bs[buf][wx * 32 + ntp * 16 + nsel][bcsel]);
        #pragma unroll
        for (int kb = 0; kb < 4; kb++) {
            unsigned afr[4][4], bfr[2][4];
            #pragma unroll
            for (int mt = 0; mt < 4; mt++) ldsm4(afr[mt], abase[mt] + kb * 32);
            #pragma unroll
            for (int ntp = 0; ntp < 2; ntp++) ldsm4(bfr[ntp], bbase[ntp] + kb * 32);
            #pragma unroll
            for (int mt = 0; mt < 4; mt++)
                #pragma unroll
                for (int nt = 0; nt < 4; nt++)
                    mma_bf16(acc[mt][nt], afr[mt], &bfr[nt >> 1][(nt & 1) * 2]);
        }
        buf = (buf == 2) ? 0 : buf + 1;
    }

    if (zi == 2) {
        __syncthreads();
        __nv_bfloat16* st = (__nv_bfloat16*)S->As;   // pitch 130 bf16
        #pragma unroll
        for (int mt = 0; mt < 4; mt++)
            #pragma unroll
            for (int nt = 0; nt < 4; nt++) {
                int cl = wx * 32 + nt * 8 + q * 2;
                float b0 = bias[j0 + cl], b1 = bias[j0 + cl + 1];
                #pragma unroll
                for (int half = 0; half < 2; half++) {
                    int rl = wy * 64 + mt * 16 + g + half * 8;
                    *(unsigned*)&st[rl * 130 + cl] =
                        pack_bf16(acc[mt][nt][half * 2 + 0] + b0,
                                  acc[mt][nt][half * 2 + 1] + b1);
                }
            }
        __syncthreads();
        int b_ = i0 >> 10;
        int irow = i0 & 1023;
        #pragma unroll
        for (int rep = 0; rep < 32; rep++) {
            int dp = rep * 4 + (tid >> 6);
            int m2 = (tid & 63) * 2;
            int gc = j0 + dp;
            int h_ = gc >> 6, d_ = gc & 63;
            __nv_bfloat162 hh;
            hh.x = st[m2 * 130 + dp];
            hh.y = st[(m2 + 1) * 130 + dp];
            *(unsigned*)&g_vt[(((size_t)(b_ * 8 + h_)) * 64 + d_) * 1024 + irow + m2] =
                *(unsigned*)&hh;
        }
        gdc_launch();
        return;
    }

    #pragma unroll
    for (int mt = 0; mt < 4; mt++)
        #pragma unroll
        for (int nt = 0; nt < 4; nt++) {
            int c = j0 + wx * 32 + nt * 8 + q * 2;
            float b0 = bias ? bias[c] : 0.f;
            float b1 = bias ? bias[c + 1] : 0.f;
            #pragma unroll
            for (int half = 0; half < 2; half++) {
                int rr = i0 + wy * 64 + mt * 16 + g + half * 8;
                if (rr >= M) continue;
                float e0 = acc[mt][nt][half * 2 + 0] + b0;
                float e1 = acc[mt][nt][half * 2 + 1] + b1;
                if (zi == 0)
                    *(float2*)&g_q[(size_t)rr * 512 + c] = make_float2(e0, e1);
                else if (zi == 1)
                    ((unsigned*)g_kb)[((size_t)rr * 512 + c) >> 1] = pack_bf16(e0, e1);
                else
                    ((unsigned*)g_pb)[((size_t)rr * 512 + c) >> 1] = pack_bf16(e0, e1);
            }
        }
    gdc_launch();
}

// ---------------- fp16 output projection: out = o @ Wo^T + bo + x ----------------
// x + Wo chunk0 prefetched BEFORE the PDL wait (they don't depend on flash)
struct POSmem {
    unsigned As[2][64][36];
    unsigned Bs[2][128][36];
    float Xs[64][132];    // pitch 132 floats = 528 B (16B multiple for cp.async)
};

__device__ __forceinline__ void pout_loadA(POSmem* S, int buf, int i0, int kk, int tid) {
    #pragma unroll
    for (int p = 0; p < 2; p++) {
        int idx = p * 256 + tid;
        int r = idx >> 3, c4 = (idx & 7) * 4;
        cpasync16(&S->As[buf][r][c4], &g_oh[(size_t)(i0 + r) * 512 + kk + c4 * 2], true);
    }
}
__device__ __forceinline__ void pout_loadB(POSmem* S, int buf, int j0, int kk, int tid) {
    #pragma unroll
    for (int p = 0; p < 4; p++) {
        int idx = p * 256 + tid;
        int r = idx >> 3, c4 = (idx & 7) * 4;
        cpasync16(&S->Bs[buf][r][c4], &g_wto[(size_t)(j0 + r) * 512 + kk + c4 * 2], true);
    }
}

__global__ void __launch_bounds__(256, 2) projout_kernel(
        const float* __restrict__ bo, const float* __restrict__ x,
        float* __restrict__ out) {
    extern __shared__ char raw[];
    POSmem* S = (POSmem*)raw;
    int i0 = blockIdx.y * 64, j0 = blockIdx.x * 128;
    int tid = threadIdx.x;
    int warp = tid >> 5, lane = tid & 31;
    int wy = warp >> 2, wx = warp & 3;
    int g = lane >> 2, q = lane & 3;
    int rsel = lane & 15;
    int csel = (lane & 16) ? 4 : 0;
    int nsel = (lane & 7) + ((lane & 16) ? 8 : 0);
    int bcsel = (lane & 8) ? 4 : 0;
    float acc[2][4][4] = {};

    // ---- pre-wait prefetch: residual x tile + Wo chunk 0 (independent of flash) ----
    #pragma unroll
    for (int p = 0; p < 8; p++) {
        int idx = p * 256 + tid;
        int r = idx >> 5, c4 = (idx & 31) * 4;
        cpasync16(&S->Xs[r][c4], &x[(size_t)(i0 + r) * 512 + j0 + c4], true);
    }
    pout_loadB(S, 0, j0, 0, tid);
    asm volatile("cp.async.commit_group;");

    gdc_wait();   // flash must complete before reading g_oh

    pout_loadA(S, 0, i0, 0, tid);
    asm volatile("cp.async.commit_group;");
    for (int s = 0; s < 8; s++) {
        asm volatile("cp.async.wait_group 0;");
        __syncthreads();
        if (s < 7) {
            pout_loadA(S, (s + 1) & 1, i0, (s + 1) * 64, tid);
            pout_loadB(S, (s + 1) & 1, j0, (s + 1) * 64, tid);
            asm volatile("cp.async.commit_group;");
        }
        int buf = s & 1;
        unsigned abase[2], bbase[2];
        #pragma unroll
        for (int mt = 0; mt < 2; mt++)
            abase[mt] = sptr(&S->As[buf][wy * 32 + mt * 16 + rsel][csel]);
        #pragma unroll
        for (int ntp = 0; ntp < 2; ntp++)
            bbase[ntp] = sptr(&S->Bs[buf][wx * 32 + ntp * 16 + nsel][bcsel]);
        #pragma unroll
        for (int kb = 0; kb < 4; kb++) {
            unsigned afr[2][4], bfr[2][4];
            #pragma unroll
            for (int mt = 0; mt < 2; mt++) ldsm4(afr[mt], abase[mt] + kb * 32);
            #pragma unroll
            for (int ntp = 0; ntp < 2; ntp++) ldsm4(bfr[ntp], bbase[ntp] + kb * 32);
            #pragma unroll
            for (int mt = 0; mt < 2; mt++)
                #pragma unroll
                for (int nt = 0; nt < 4; nt++)
                    mma_f16(acc[mt][nt], afr[mt], &bfr[nt >> 1][(nt & 1) * 2]);
        }
    }
    #pragma unroll
    for (int mt = 0; mt < 2; mt++)
        #pragma unroll
        for (int nt = 0; nt < 4; nt++) {
            int cl = wx * 32 + nt * 8 + q * 2;
            int c = j0 + cl;
            float b0 = bo[c], b1 = bo[c + 1];
            #pragma unroll
            for (int half = 0; half < 2; half++) {
                int rl = wy * 32 + mt * 16 + g + half * 8;
                int rr = i0 + rl;
                float e0 = acc[mt][nt][half * 2 + 0] + b0 + S->Xs[rl][cl];
                float e1 = acc[mt][nt][half * 2 + 1] + b1 + S->Xs[rl][cl + 1];
                *(float2*)&out[(size_t)rr * 512 + c] = make_float2(e0, e1);
            }
        }
}

// ---------------- flash attention: bf16 k16, 64-row tiles, 4 warps, 2 CTAs/SM ----------------
struct FlashSmem {
    unsigned Ks[2][64][36];
    unsigned Ps[2][64][36];
    unsigned Vt[2][64][36];
    __nv_bfloat16 R[64][264];
    float Qs[64][68];
    float cbS[64], pbS[64];
};

__device__ __forceinline__ void pos_chunk(FlashSmem* S, int stage, int cbase,
                                          const unsigned apf[4][4], int row0,
                                          int nsel, int bcsel, int q) {
    float accP[8][4] = {};
    #pragma unroll
    for (int ntp = 0; ntp < 4; ntp++) {
        unsigned base = sptr(&S->Ps[stage][ntp * 16 + nsel][bcsel]);
        #pragma unroll
        for (int kb = 0; kb < 4; kb++) {
            unsigned bfr[4];
            ldsm4(bfr, base + kb * 32);
            mma_bf16(accP[ntp * 2],     apf[kb], bfr);
            mma_bf16(accP[ntp * 2 + 1], apf[kb], bfr + 2);
        }
    }
    #pragma unroll
    for (int nt = 0; nt < 8; nt++) {
        int s0 = (cbase + nt * 8 + 2 * q) & 255;
        *(__nv_bfloat162*)&S->R[row0][s0]     = __floats2bfloat162_rn(accP[nt][0], accP[nt][1]);
        *(__nv_bfloat162*)&S->R[row0 + 8][s0] = __floats2bfloat162_rn(accP[nt][2], accP[nt][3]);
    }
}

__global__ void __launch_bounds__(128, 2) flash_kernel(const float* __restrict__ cb,
                                                       const float* __restrict__ pb) {
    extern __shared__ char raw[];
    FlashSmem* S = (FlashSmem*)raw;
    gdc_wait();
    int z = blockIdx.y; int b = z >> 3, h = z & 7;
    int i0 = blockIdx.x * 64;
    int tid = threadIdx.x;
    int warp = tid >> 5, lane = tid & 31;
    int g = lane >> 2, q = lane & 3;
    int row0 = warp * 16 + g;
    int nsel = (lane & 7) + ((lane & 16) ? 8 : 0);
    int bcsel = (lane & 8) ? 4 : 0;
    const int base0 = 1024 - i0 - 128;

    const float* qsrc = g_q + ((size_t)(b * T + i0)) * D + h * 64;
    #pragma unroll
    for (int p = 0; p < 8; p++) {
        int idx = p * 128 + tid;
        int r = idx >> 4, c4 = (idx & 15) * 4;
        cpasync16(&S->Qs[r][c4], &qsrc[(size_t)r * D + c4], true);
    }
    #pragma unroll
    for (int p = 0; p < 4; p++) {
        int idx = p * 128 + tid;
        int r = idx >> 3, c8 = (idx & 7) * 8;
        int l0 = base0 + r;      l0 = min(max(l0, 0), LL - 1);
        int l1 = base0 + 64 + r; l1 = min(max(l1, 0), LL - 1);
        cpasync16(&S->Ps[0][r][c8 >> 1], &g_pb[((size_t)(b * LL + l0)) * D + h * 64 + c8], true);
        cpasync16(&S->Ps[1][r][c8 >> 1], &g_pb[((size_t)(b * LL + l1)) * D + h * 64 + c8], true);
    }
    asm volatile("cp.async.commit_group;");
    if (tid < 16) {
        *(float4*)&S->cbS[tid * 4] = *(const float4*)&cb[h * 64 + tid * 4];
        *(float4*)&S->pbS[tid * 4] = *(const float4*)&pb[h * 64 + tid * 4];
    }

    float gfixv = 0.f;
    if (i0 == 0 && warp == 0) {
        float a0 = __bfloat162float(__float2bfloat16_rn(
            g_q[((size_t)(b * T + 1)) * D + h * 64 + lane] + pb[h * 64 + lane]));
        float a1 = __bfloat162float(__float2bfloat16_rn(
            g_q[((size_t)(b * T + 1)) * D + h * 64 + lane + 32] + pb[h * 64 + lane + 32]));
        float p0 = __bfloat162float(g_pb[((size_t)(b * LL)) * D + h * 64 + lane]);
        float p1 = __bfloat162float(g_pb[((size_t)(b * LL)) * D + h * 64 + lane + 32]);
        float sd = a0 * p0 + a1 * p1;
        #pragma unroll
        for (int o = 16; o > 0; o >>= 1) sd += __shfl_xor_sync(0xFFFFFFFFu, sd, o);
        gfixv = sd;
    }

    asm volatile("cp.async.wait_group 0;");
    __syncthreads();

    unsigned acf[4][4], apf[4][4];
    #pragma unroll
    for (int kb = 0; kb < 4; kb++) {
        int k0 = kb * 16 + 2 * q;
        float q00 = S->Qs[row0][k0],       q01 = S->Qs[row0][k0 + 1];
        float q10 = S->Qs[row0 + 8][k0],   q11 = S->Qs[row0 + 8][k0 + 1];
        float q02 = S->Qs[row0][k0 + 8],   q03 = S->Qs[row0][k0 + 9];
        float q12 = S->Qs[row0 + 8][k0 + 8], q13 = S->Qs[row0 + 8][k0 + 9];
        float c0 = S->cbS[k0], c1 = S->cbS[k0 + 1], c8v = S->cbS[k0 + 8], c9 = S->cbS[k0 + 9];
        float p0 = S->pbS[k0], p1 = S->pbS[k0 + 1], p8 = S->pbS[k0 + 8], p9 = S->pbS[k0 + 9];
        acf[kb][0] = pack_bf16(q00 + c0, q01 + c1);
        acf[kb][1] = pack_bf16(q10 + c0, q11 + c1);
        acf[kb][2] = pack_bf16(q02 + c8v, q03 + c9);
        acf[kb][3] = pack_bf16(q12 + c8v, q13 + c9);
        apf[kb][0] = pack_bf16(q00 + p0, q01 + p1);
        apf[kb][1] = pack_bf16(q10 + p0, q11 + p1);
        apf[kb][2] = pack_bf16(q02 + p8, q03 + p9);
        apf[kb][3] = pack_bf16(q12 + p8, q13 + p9);
    }

    pos_chunk(S, 0, base0, apf, row0, nsel, bcsel, q);
    pos_chunk(S, 1, base0 + 64, apf, row0, nsel, bcsel, q);
    __syncthreads();
    #pragma unroll
    for (int p = 0; p < 4; p++) {
        int idx = p * 128 + tid;
        int r = idx >> 3, c8 = (idx & 7) * 8;
        int l = base0 + 128 + r; l = min(max(l, 0), LL - 1);
        cpasync16(&S->Ps[0][r][c8 >> 1], &g_pb[((size_t)(b * LL + l)) * D + h * 64 + c8], true);
    }
    asm volatile("cp.async.commit_group;");
    asm volatile("cp.async.wait_group 0;");
    __syncthreads();
    pos_chunk(S, 0, base0 + 128, apf, row0, nsel, bcsel, q);
    __syncthreads();

    {
        const __nv_bfloat16* kb_ = g_kb + ((size_t)(b * T)) * D + h * 64;
        const __nv_bfloat16* vt_ = g_vt + ((size_t)z) * 64 * 1024;
        #pragma unroll
        for (int p = 0; p < 4; p++) {
            int idx = p * 128 + tid;
            int r = idx >> 3, c8 = (idx & 7) * 8;
            cpasync16(&S->Ks[0][r][c8 >> 1], &kb_[(size_t)r * D + c8], true);
            cpasync16(&S->Vt[0][r][c8 >> 1], &vt_[(size_t)r * 1024 + c8], true);
            int l = base0 + 192 + r; l = min(max(l, 0), LL - 1);
            cpasync16(&S->Ps[0][r][c8 >> 1], &g_pb[((size_t)(b * LL + l)) * D + h * 64 + c8], true);
        }
        asm volatile("cp.async.commit_group;");
    }

    float accO[8][4] = {};
    float sumA = 0.f, sumB = 0.f;

    for (int jt = 0; jt < 16; jt++) {
        asm volatile("cp.async.wait_group 0;");
        __syncthreads();
        int st = jt & 1;
        if (jt < 15) {
            int st2 = st ^ 1;
            const __nv_bfloat16* kb_ = g_kb + ((size_t)(b * T + (jt + 1) * 64)) * D + h * 64;
            const __nv_bfloat16* vt_ = g_vt + ((size_t)z) * 64 * 1024 + (jt + 1) * 64;
            #pragma unroll
            for (int p = 0; p < 4; p++) {
                int idx = p * 128 + tid;
                int r = idx >> 3, c8 = (idx & 7) * 8;
                cpasync16(&S->Ks[st2][r][c8 >> 1], &kb_[(size_t)r * D + c8], true);
                cpasync16(&S->Vt[st2][r][c8 >> 1], &vt_[(size_t)r * 1024 + c8], true);
                int l = base0 + 192 + 64 * (jt + 1) + r; l = min(max(l, 0), LL - 1);
                cpasync16(&S->Ps[st2][r][c8 >> 1], &g_pb[((size_t)(b * LL + l)) * D + h * 64 + c8], true);
            }
            asm volatile("cp.async.commit_group;");
        }

        float accC[8][4] = {};
        #pragma unroll
        for (int ntp = 0; ntp < 4; ntp++) {
            unsigned base = sptr(&S->Ks[st][ntp * 16 + nsel][bcsel]);
            #pragma unroll
            for (int kb2 = 0; kb2 < 4; kb2++) {
                unsigned bfr[4];
                ldsm4(bfr, base + kb2 * 32);
                mma_bf16(accC[ntp * 2],     acf[kb2], bfr);
                mma_bf16(accC[ntp * 2 + 1], acf[kb2], bfr + 2);
            }
        }
        if (jt < 15) pos_chunk(S, st, base0 + 192 + 64 * jt, apf, row0, nsel, bcsel, q);

        unsigned vbase[4];
        #pragma unroll
        for (int n2p = 0; n2p < 4; n2p++)
            vbase[n2p] = sptr(&S->Vt[st][n2p * 16 + nsel][bcsel]);

        int basew = 1024 + 64 * jt - i0;
        bool fixc = (i0 == 0) && (jt == 15) && (warp == 0) && (g == 0) && (q == 3);
        #pragma unroll
        for (int kb2 = 0; kb2 < 4; kb2++) {
            unsigned a[4];
            #pragma unroll
            for (int half = 0; half < 2; half++) {
                int nt = kb2 * 2 + half;
                int jl = nt * 8 + 2 * q;
                int il0 = row0, il1 = row0 + 8;
                float r00 = __bfloat162float(S->R[il0][(basew + jl - il0) & 255]);
                float r01 = __bfloat162float(S->R[il0][(basew + jl + 1 - il0) & 255]);
                float r10 = __bfloat162float(S->R[il1][(basew + jl - il1) & 255]);
                float r11 = __bfloat162float(S->R[il1][(basew + jl + 1 - il1) & 255]);
                if (fixc && nt == 7) r01 = gfixv;
                float e0 = __expf((accC[nt][0] + r00) * 0.125f);
                float e1 = __expf((accC[nt][1] + r01) * 0.125f);
                float e2 = __expf((accC[nt][2] + r10) * 0.125f);
                float e3 = __expf((accC[nt][3] + r11) * 0.125f);
                sumA += e0 + e1; sumB += e2 + e3;
                a[half * 2]     = pack_bf16(e0, e1);
                a[half * 2 + 1] = pack_bf16(e2, e3);
            }
            #pragma unroll
            for (int n2p = 0; n2p < 4; n2p++) {
                unsigned vfr[4];
                ldsm4(vfr, vbase[n2p] + kb2 * 32);
                mma_bf16(accO[n2p * 2],     a, vfr);
                mma_bf16(accO[n2p * 2 + 1], a, vfr + 2);
            }
        }
    }

    sumA += __shfl_xor_sync(0xFFFFFFFFu, sumA, 1);
    sumA += __shfl_xor_sync(0xFFFFFFFFu, sumA, 2);
    sumB += __shfl_xor_sync(0xFFFFFFFFu, sumB, 1);
    sumB += __shfl_xor_sync(0xFFFFFFFFu, sumB, 2);
    float invA = 1.f / sumA, invB = 1.f / sumB;
    #pragma unroll
    for (int n2 = 0; n2 < 8; n2++) {
        int col = h * 64 + n2 * 8 + 2 * q;
        size_t r = (size_t)(b * T + i0 + row0);
        __half2 h0 = __floats2half2_rn(accO[n2][0] * invA, accO[n2][1] * invA);
        __half2 h1 = __floats2half2_rn(accO[n2][2] * invB, accO[n2][3] * invB);
        *(unsigned*)&g_oh[r * D + col] = *(unsigned*)&h0;
        *(unsigned*)&g_oh[(r + 8) * D + col] = *(unsigned*)&h1;
    }
    gdc_launch();
}

extern "C" void kernel_launch(void* const* d_in, const int* in_sizes, int n_in,
                              void* d_out, int out_size) {
    const float* x     = (const float*)d_in[0];
    const float* pos   = (const float*)d_in[1];
    const float* cb    = (const float*)d_in[2];
    const float* pb    = (const float*)d_in[3];
    const float* gamma = (const float*)d_in[4];
    const float* beta  = (const float*)d_in[5];
    const float* Wq    = (const float*)d_in[6];
    const float* bq    = (const float*)d_in[7];
    const float* Wk    = (const float*)d_in[8];
    const float* bk    = (const float*)d_in[9];
    const float* Wv    = (const float*)d_in[10];
    const float* bv    = (const float*)d_in[11];
    const float* Wp    = (const float*)d_in[12];
    const float* Wo    = (const float*)d_in[13];
    const float* bo    = (const float*)d_in[14];
    float* out = (float*)d_out;

    cudaFuncSetAttribute(projall_kernel, cudaFuncAttributeMaxDynamicSharedMemorySize,
                         (int)sizeof(PSmem));
    cudaFuncSetAttribute(projout_kernel, cudaFuncAttributeMaxDynamicSharedMemorySize,
                         (int)sizeof(POSmem));
    cudaFuncSetAttribute(flash_kernel, cudaFuncAttributeMaxDynamicSharedMemorySize,
                         (int)sizeof(FlashSmem));

    // PDL launch attribute
    cudaLaunchAttribute pdl[1];
    pdl[0].id = cudaLaunchAttributeProgrammaticStreamSerialization;
    pdl[0].val.programmaticStreamSerializationAllowed = 1;

    // 1. merged prep: 5 weight transposes + pos convert (float4) + LayerNorm
    prep_kernel<<<9470, 256>>>(x, gamma, beta, pos, Wq, Wk, Wv, Wp, Wo);

    // 2. unified projections (q/k/v/pos, bf16, ldmatrix, 3-stage pipeline)
    {
        cudaLaunchConfig_t cfg = {};
        cfg.gridDim = dim3(4, 160);
        cfg.blockDim = dim3(256);
        cfg.dynamicSmemBytes = sizeof(PSmem);
        cfg.attrs = pdl; cfg.numAttrs = 1;
        cudaLaunchKernelEx(&cfg, projall_kernel, bq, bk, bv);
    }

    // 3. fused flash attention (64-row tiles, 2 CTAs/SM)
    {
        cudaLaunchConfig_t cfg = {};
        cfg.gridDim = dim3(16, 32);
        cfg.blockDim = dim3(128);
        cfg.dynamicSmemBytes = sizeof(FlashSmem);
        cfg.attrs = pdl; cfg.numAttrs = 1;
        cudaLaunchKernelEx(&cfg, flash_kernel, cb, pb);
    }

    // 4. output projection (fp16 mma) + bias + residual (x/Wo pre-wait prefetched)
    {
        cudaLaunchConfig_t cfg = {};
        cfg.gridDim = dim3(4, 64);
        cfg.blockDim = dim3(256);
        cfg.dynamicSmemBytes = sizeof(POSmem);
        cfg.attrs = pdl; cfg.numAttrs = 1;
        cudaLaunchKernelEx(&cfg, projout_kernel, bo, x, out);
    }
}